// round 10
// baseline (speedup 1.0000x reference)
#include <cuda_runtime.h>
#include <cstddef>
#include <cstdint>

#define TLEN 512
#define NB   64
#define UDIM 256
#define GDIM 768
#define EDIM 300
#define CDIM 20
#define KP   260   // rk smem row pad: lane stride 1040B -> conflict-free LDS.128

__device__ float g_xw[(size_t)2 * NB * TLEN * GDIM];   // [dir][b*T+t][g]
__device__ float g_h1[(size_t)NB * TLEN * 2 * UDIM];   // [b*T+t][2U]
__device__ float g_h2[NB * 2 * UDIM];

__device__ __forceinline__ unsigned long long ffma2(unsigned long long a,
                                                    unsigned long long b,
                                                    unsigned long long c) {
    unsigned long long d;
    asm("fma.rn.f32x2 %0,%1,%2,%3;" : "=l"(d) : "l"(a), "l"(b), "l"(c));
    return d;
}
__device__ __forceinline__ unsigned long long dup2(float x) {
    unsigned long long d;
    asm("mov.b64 %0,{%1,%1};" : "=l"(d) : "r"(__float_as_uint(x)));
    return d;
}
union F4U { float4 v; float f[4]; unsigned long long u[2]; };

__device__ __forceinline__ uint32_t smem_u32(const void* p) {
    uint32_t a;
    asm("{ .reg .u64 t; cvta.to.shared.u64 t, %1; cvt.u32.u64 %0, t; }"
        : "=r"(a) : "l"(p));
    return a;
}
__device__ __forceinline__ uint32_t mapa_u32(uint32_t a, uint32_t rank) {
    uint32_t d;
    asm("mapa.shared::cluster.u32 %0, %1, %2;" : "=r"(d) : "r"(a), "r"(rank));
    return d;
}
__device__ __forceinline__ void sts_cl_f4(uint32_t a, float4 v) {
    asm volatile("st.shared::cluster.v4.f32 [%0], {%1,%2,%3,%4};"
                 :: "r"(a), "f"(v.x), "f"(v.y), "f"(v.z), "f"(v.w) : "memory");
}
#define CL_ARRIVE() asm volatile("barrier.cluster.arrive.aligned;" ::: "memory")
#define CL_WAIT()   asm volatile("barrier.cluster.wait.aligned;" ::: "memory")

// inf-safe fast activations (MUFU ex2/rcp based)
__device__ __forceinline__ float fsig(float x) {
    return __fdividef(1.0f, 1.0f + __expf(-x));
}
__device__ __forceinline__ float ftanh(float x) {
    return 1.0f - __fdividef(2.0f, 1.0f + __expf(2.0f * x));
}

// ============================ GEMM (unchanged) ==========================
#define BM 128
#define BN 128
#define BK 8

__global__ __launch_bounds__(256, 2)
void gemm_kernel(int mode, const int* __restrict__ gidx, const float* __restrict__ emb,
                 const float* __restrict__ Wf, const float* __restrict__ Wb,
                 const float* __restrict__ bf, const float* __restrict__ bb, int K)
{
    const int tid = threadIdx.x;
    const int dir = blockIdx.z;
    const float* __restrict__ W    = dir ? Wb : Wf;
    const float* __restrict__ bias = dir ? bb : bf;
    float* outp = g_xw + (size_t)dir * NB * TLEN * GDIM;
    const int bm = blockIdx.y * BM, bn = blockIdx.x * BN;

    __shared__ float As[BK][BM + 4];
    __shared__ float Bs[BK][BN];

    const int a_m = tid >> 1, a_k = (tid & 1) * 4;
    const int b_k = tid >> 5, b_n = (tid & 31) * 4;
    const int tx = tid & 15, ty = tid >> 4;

    const float* arow = mode ? (g_h1 + (size_t)(bm + a_m) * (2 * UDIM))
                             : (emb + (size_t)gidx[bm + a_m] * EDIM);

    unsigned long long acc[8][4];
#pragma unroll
    for (int i = 0; i < 8; i++)
#pragma unroll
        for (int j = 0; j < 4; j++) acc[i][j] = 0ull;

    for (int k0 = 0; k0 < K; k0 += BK) {
        if (k0 + a_k + 4 <= K) {
            F4U t; t.v = *(const float4*)(arow + k0 + a_k);
            As[a_k + 0][a_m] = t.f[0]; As[a_k + 1][a_m] = t.f[1];
            As[a_k + 2][a_m] = t.f[2]; As[a_k + 3][a_m] = t.f[3];
        } else {
#pragma unroll
            for (int i = 0; i < 4; i++) {
                int kk = k0 + a_k + i;
                As[a_k + i][a_m] = (kk < K) ? arow[kk] : 0.0f;
            }
        }
        {
            int kk = k0 + b_k;
            float4 bv = make_float4(0.f, 0.f, 0.f, 0.f);
            if (kk < K) bv = *(const float4*)(W + (size_t)kk * GDIM + bn + b_n);
            *(float4*)&Bs[b_k][b_n] = bv;
        }
        __syncthreads();
#pragma unroll
        for (int kk = 0; kk < BK; kk++) {
            F4U a0, a1, b0, b1;
            a0.v = *(const float4*)&As[kk][ty * 4];
            a1.v = *(const float4*)&As[kk][64 + ty * 4];
            b0.v = *(const float4*)&Bs[kk][tx * 4];
            b1.v = *(const float4*)&Bs[kk][64 + tx * 4];
            unsigned long long ap[8];
            unsigned long long bp[4] = { b0.u[0], b0.u[1], b1.u[0], b1.u[1] };
#pragma unroll
            for (int i = 0; i < 4; i++) { ap[i] = dup2(a0.f[i]); ap[4 + i] = dup2(a1.f[i]); }
#pragma unroll
            for (int i = 0; i < 8; i++)
#pragma unroll
                for (int j = 0; j < 4; j++)
                    acc[i][j] = ffma2(ap[i], bp[j], acc[i][j]);
        }
        __syncthreads();
    }
#pragma unroll
    for (int i = 0; i < 8; i++) {
        int m = bm + ((i < 4) ? (ty * 4 + i) : (64 + ty * 4 + i - 4));
        float* orow = outp + (size_t)m * GDIM + bn;
#pragma unroll
        for (int j = 0; j < 4; j++) {
            int c = (j < 2) ? (tx * 4 + j * 2) : (64 + tx * 4 + (j - 2) * 2);
            F4U t; t.u[0] = acc[i][j];
            float2 r;
            r.x = t.f[0] + bias[bn + c];
            r.y = t.f[1] + bias[bn + c + 1];
            *(float2*)(orow + c) = r;
        }
    }
}

// ===================== Recurrence v3: DSMEM cluster ======================
// 16 clusters of 8 CTAs; cluster = (dir, batch-group), rank = unit-slice.
// 256 thr = kq(4) x bq(2) x j(32). Double-buffered h in smem; each step every
// CTA pushes its hn slice to all 8 ranks via st.shared::cluster, then
// barrier.cluster arrive/wait. No global atomics, no h reload.
#define H_F   2048                      // floats per h buffer (8 b x 256 u)
#define STG_F 256
#define RED_F (3 * 2 * 32 * 12)
#define REC_SMEM ((96 * KP + 2 * H_F + STG_F + RED_F) * 4)

__global__ __launch_bounds__(256, 1) __cluster_dims__(8, 1, 1)
void rec_kernel(const float* __restrict__ rkf, const float* __restrict__ rkb,
                const float* __restrict__ rbf, const float* __restrict__ rbb,
                int layer)
{
    extern __shared__ float sm[];
    float* rk_s = sm;                     // [96][KP]
    float* hbuf = sm + 96 * KP;           // [2][8][256]
    float* stg  = hbuf + 2 * H_F;         // [8][32]
    float* red  = stg + STG_F;            // [3][2][32][12]
    const int blk = blockIdx.x, dir = blk >> 6, bg = (blk >> 3) & 7, us = blk & 7;
    const int tid = threadIdx.x;
    const int kq = tid >> 6, bq = (tid >> 5) & 1, j = tid & 31;
    const float* __restrict__ rk = dir ? rkb : rkf;
    const float* __restrict__ rb = dir ? rbb : rbf;

    for (int i = tid; i < 96 * 256; i += 256) {
        int k = i / 96, c = i - k * 96;
        rk_s[c * KP + k] = rk[(size_t)k * GDIM + (c >> 5) * UDIM + us * 32 + (c & 31)];
    }
    for (int i = tid; i < 2 * H_F; i += 256) hbuf[i] = 0.0f;
    __syncthreads();

    // broadcast-address precompute: thread handles float4 f0=tid, f1=tid+256
    // (f = rank*64 + b*8 + q): dst = h_next[b*256 + us*32 + q*4] on CTA 'rank'.
    const uint32_t h0u = smem_u32(hbuf), h1u = h0u + H_F * 4;
    const int f0 = tid, f1 = tid + 256;
    const int r0 = f0 >> 6, r1 = f1 >> 6, fi0 = f0 & 63, fi1 = f1 & 63;
    const int off0 = (((fi0 >> 3) << 8) + us * 32 + ((fi0 & 7) << 2)) * 4;
    const int off1 = (((fi1 >> 3) << 8) + us * 32 + ((fi1 & 7) << 2)) * 4;
    const uint32_t d0_even = mapa_u32(h1u + off0, r0), d1_even = mapa_u32(h1u + off1, r1);
    const uint32_t d0_odd  = mapa_u32(h0u + off0, r0), d1_odd  = mapa_u32(h0u + off1, r1);

    const int u = us * 32 + j;
    const int kb = kq * 64;
    const float rbz = rb[u], rbr = rb[UDIM + u], rbh = rb[2 * UDIM + u];
    const float* xwd = g_xw + (size_t)dir * NB * TLEN * GDIM;
    const float* rzp = rk_s + (size_t)j * KP + kb;
    const float* rrp = rk_s + (size_t)(32 + j) * KP + kb;
    const float* rhp = rk_s + (size_t)(64 + j) * KP + kb;

    CL_ARRIVE(); CL_WAIT();   // peers resident + their smem initialized

    for (int s = 0; s < TLEN; s++) {
        const int t = dir ? (TLEN - 1 - s) : s;
        const float* hpb = hbuf + (s & 1) * H_F + (bq * 4) * 256 + kb;

        float xz[4], xr[4], xh[4];
        if (kq == 0) {
#pragma unroll
            for (int i = 0; i < 4; i++) {
                const float* xr0 = xwd + ((size_t)(bg * 8 + bq * 4 + i) * TLEN + t) * GDIM;
                xz[i] = __ldg(xr0 + u);
                xr[i] = __ldg(xr0 + UDIM + u);
                xh[i] = __ldg(xr0 + 2 * UDIM + u);
            }
        }

        unsigned long long az[4], ar[4], ah[4];
#pragma unroll
        for (int i = 0; i < 4; i++) { az[i] = 0ull; ar[i] = 0ull; ah[i] = 0ull; }

#pragma unroll 4
        for (int k = 0; k < 64; k += 4) {
            F4U vz, vr, vh;
            vz.v = *(const float4*)(rzp + k);
            vr.v = *(const float4*)(rrp + k);
            vh.v = *(const float4*)(rhp + k);
#pragma unroll
            for (int i = 0; i < 4; i++) {
                F4U hv; hv.v = *(const float4*)(hpb + i * 256 + k);
                az[i] = ffma2(vz.u[0], hv.u[0], az[i]);
                az[i] = ffma2(vz.u[1], hv.u[1], az[i]);
                ar[i] = ffma2(vr.u[0], hv.u[0], ar[i]);
                ar[i] = ffma2(vr.u[1], hv.u[1], ar[i]);
                ah[i] = ffma2(vh.u[0], hv.u[0], ah[i]);
                ah[i] = ffma2(vh.u[1], hv.u[1], ah[i]);
            }
        }

        float sz[4], sr[4], sh[4];
#pragma unroll
        for (int i = 0; i < 4; i++) {
            F4U a; a.u[0] = az[i]; sz[i] = a.f[0] + a.f[1];
            a.u[0] = ar[i];        sr[i] = a.f[0] + a.f[1];
            a.u[0] = ah[i];        sh[i] = a.f[0] + a.f[1];
        }

        if (kq != 0) {
            float* rp = red + (((kq - 1) * 2 + bq) * 32 + j) * 12;
            *(float4*)(rp + 0) = make_float4(sz[0], sz[1], sz[2], sz[3]);
            *(float4*)(rp + 4) = make_float4(sr[0], sr[1], sr[2], sr[3]);
            *(float4*)(rp + 8) = make_float4(sh[0], sh[1], sh[2], sh[3]);
        }
        __syncthreads();

        float hn[4];
        if (kq == 0) {
#pragma unroll
            for (int q = 0; q < 3; q++) {
                const float* rp = red + ((q * 2 + bq) * 32 + j) * 12;
                float4 a = *(const float4*)(rp + 0);
                float4 b = *(const float4*)(rp + 4);
                float4 c = *(const float4*)(rp + 8);
                sz[0] += a.x; sz[1] += a.y; sz[2] += a.z; sz[3] += a.w;
                sr[0] += b.x; sr[1] += b.y; sr[2] += b.z; sr[3] += b.w;
                sh[0] += c.x; sh[1] += c.y; sh[2] += c.z; sh[3] += c.w;
            }
            const float* hold = hbuf + (s & 1) * H_F;
#pragma unroll
            for (int i = 0; i < 4; i++) {
                const int bL = bq * 4 + i;
                float z = fsig(xz[i] + rbz + sz[i]);
                float r = fsig(xr[i] + rbr + sr[i]);
                float hh = ftanh(xh[i] + rbh + r * sh[i]);
                hn[i] = z * hold[bL * 256 + u] + (1.f - z) * hh;
                stg[bL * 32 + j] = hn[i];
            }
        }
        __syncthreads();

        // all-rank broadcast of this CTA's slice (2 float4 per thread)
        {
            float4 v0 = *(const float4*)(stg + fi0 * 4);
            float4 v1 = *(const float4*)(stg + fi1 * 4);
            if (s & 1) { sts_cl_f4(d0_odd, v0);  sts_cl_f4(d1_odd, v1); }
            else       { sts_cl_f4(d0_even, v0); sts_cl_f4(d1_even, v1); }
        }
        CL_ARRIVE();

        if (kq == 0) {        // off-critical-path global stores
            if (layer == 1) {
#pragma unroll
                for (int i = 0; i < 4; i++) {
                    const int Bg = bg * 8 + bq * 4 + i;
                    g_h1[((size_t)Bg * TLEN + t) * (2 * UDIM) + dir * UDIM + u] = hn[i];
                }
            } else if (s == TLEN - 1) {
#pragma unroll
                for (int i = 0; i < 4; i++) {
                    const int Bg = bg * 8 + bq * 4 + i;
                    g_h2[Bg * 2 * UDIM + dir * UDIM + u] = hn[i];
                }
            }
        }
        CL_WAIT();
    }
}

// ======================== softmax head =================================
__global__ void out_kernel(const float* __restrict__ wout, const float* __restrict__ bout,
                           float* __restrict__ out)
{
    __shared__ float h[2 * UDIM];
    const int b = blockIdx.x, t = threadIdx.x;
    for (int i = t; i < 128; i += 32)
        ((float4*)h)[i] = ((const float4*)(g_h2 + b * 2 * UDIM))[i];
    __syncwarp();
    float l = -1e30f;
    if (t < CDIM) {
        float a = bout[t];
        for (int k = 0; k < 2 * UDIM; k++) a = fmaf(h[k], wout[k * CDIM + t], a);
        l = a;
    }
    float m = l;
    for (int o = 16; o; o >>= 1) m = fmaxf(m, __shfl_xor_sync(~0u, m, o));
    float e = (t < CDIM) ? expf(l - m) : 0.0f, ssum = e;
    for (int o = 16; o; o >>= 1) ssum += __shfl_xor_sync(~0u, ssum, o);
    if (t < CDIM) out[b * CDIM + t] = e / ssum;
}

// ========================= launcher ====================================
extern "C" void kernel_launch(void* const* d_in, const int* in_sizes, int n_in,
                              void* d_out, int out_size)
{
    const int*   x    = (const int*)d_in[0];
    const float* emb  = (const float*)d_in[1];
    const float* k1f  = (const float*)d_in[2];
    const float* rk1f = (const float*)d_in[3];
    const float* b1f  = (const float*)d_in[4];
    const float* k1b  = (const float*)d_in[5];
    const float* rk1b = (const float*)d_in[6];
    const float* b1b  = (const float*)d_in[7];
    const float* k2f  = (const float*)d_in[8];
    const float* rk2f = (const float*)d_in[9];
    const float* b2f  = (const float*)d_in[10];
    const float* k2b  = (const float*)d_in[11];
    const float* rk2b = (const float*)d_in[12];
    const float* b2b  = (const float*)d_in[13];
    const float* wout = (const float*)d_in[14];
    const float* bout = (const float*)d_in[15];
    float* out = (float*)d_out;
    (void)in_sizes; (void)n_in; (void)out_size;

    cudaFuncSetAttribute(rec_kernel, cudaFuncAttributeMaxDynamicSharedMemorySize, REC_SMEM);

    dim3 gg(GDIM / BN, (NB * TLEN) / BM, 2);
    gemm_kernel<<<gg, 256>>>(0, x, emb, k1f, k1b, b1f, b1b, EDIM);
    rec_kernel<<<128, 256, REC_SMEM>>>(rk1f, rk1b, b1f + GDIM, b1b + GDIM, 1);
    gemm_kernel<<<gg, 256>>>(1, x, emb, k2f, k2b, b2f, b2b, 2 * UDIM);
    rec_kernel<<<128, 256, REC_SMEM>>>(rk2f, rk2b, b2f + GDIM, b2b + GDIM, 2);
    out_kernel<<<NB, 32>>>(wout, bout, out);
}